// round 1
// baseline (speedup 1.0000x reference)
#include <cuda_runtime.h>

// TSM (temporal shift module) for fixed shape:
//   x: [B=8, T=16, C=96, H=112, W=112] float32
//   shift_factor=0.25 -> k=4, elements=3
// Semantics (derived from reference):
//   c % 3 == 0: out[t] = (t < T-k=12) ? 0 : x[t]
//   c % 3 == 1: out[t] = (t <  k=4 ) ? 0 : x[t-k]
//   c % 3 == 2: out[t] = x[t]
// Each (b,t,c) plane = H*W = 12544 contiguous floats = 3136 float4.
// 3136 = 7 * 448 -> blockDim=448, gridDim.x=7 exactly covers a plane.

static constexpr int B = 8;
static constexpr int T = 16;
static constexpr int C = 96;
static constexpr int HW = 112 * 112;         // 12544
static constexpr int VEC_PER_PLANE = HW / 4; // 3136
static constexpr int K_SHIFT = 4;            // floor(T * 0.25)
static constexpr int PLANES = B * T * C;     // 12288
static constexpr int THREADS = 448;          // 3136 / 7

__global__ __launch_bounds__(THREADS)
void tsm_kernel(const float4* __restrict__ x, float4* __restrict__ out) {
    const int plane = blockIdx.y;
    const int off   = blockIdx.x * THREADS + threadIdx.x;  // [0, 3136)

    const int c  = plane % C;
    const int t  = (plane / C) % T;
    const int m  = c % 3;

    const long long idx = (long long)plane * VEC_PER_PLANE + off;

    float4 v;
    if (m == 2) {
        v = x[idx];
    } else if (m == 0) {
        if (t < T - K_SHIFT) {
            v = make_float4(0.f, 0.f, 0.f, 0.f);
        } else {
            v = x[idx];
        }
    } else { // m == 1
        if (t < K_SHIFT) {
            v = make_float4(0.f, 0.f, 0.f, 0.f);
        } else {
            v = x[idx - (long long)K_SHIFT * C * VEC_PER_PLANE];
        }
    }
    out[idx] = v;
}

extern "C" void kernel_launch(void* const* d_in, const int* in_sizes, int n_in,
                              void* d_out, int out_size) {
    const float4* x = (const float4*)d_in[0];
    float4* out = (float4*)d_out;

    dim3 grid(VEC_PER_PLANE / THREADS, PLANES);  // (7, 12288)
    tsm_kernel<<<grid, THREADS>>>(x, out);
}

// round 2
// speedup vs baseline: 1.0272x; 1.0272x over previous
#include <cuda_runtime.h>

// TSM (temporal shift module) for fixed shape:
//   x: [B=8, T=16, C=96, H=112, W=112] float32, k=4, elements=3
// Semantics:
//   c % 3 == 0: out[t] = (t < 12) ? 0 : x[t]
//   c % 3 == 1: out[t] = (t <  4) ? 0 : x[t-4]
//   c % 3 == 2: out[t] = x[t]
// One block per (b,t,c) plane. Plane = H*W = 12544 floats = 3136 float4.
// 448 threads x 7 vecs/thread = 3136: uniform branch per block, MLP=7.

static constexpr int B = 8;
static constexpr int T = 16;
static constexpr int C = 96;
static constexpr int HW = 112 * 112;         // 12544
static constexpr int VEC_PER_PLANE = HW / 4; // 3136
static constexpr int K_SHIFT = 4;
static constexpr int PLANES = B * T * C;     // 12288
static constexpr int THREADS = 448;
static constexpr int VPT = VEC_PER_PLANE / THREADS;  // 7

__global__ __launch_bounds__(THREADS)
void tsm_kernel(const float4* __restrict__ x, float4* __restrict__ out) {
    const int plane = blockIdx.x;
    const int c = plane % C;
    const int t = (plane / C) % T;
    const int m = c % 3;

    const long long base = (long long)plane * VEC_PER_PLANE + threadIdx.x;
    float4* __restrict__ o = out + base;

    const bool zero = (m == 0 && t < T - K_SHIFT) || (m == 1 && t < K_SHIFT);

    if (zero) {
        const float4 z = make_float4(0.f, 0.f, 0.f, 0.f);
        #pragma unroll
        for (int i = 0; i < VPT; i++)
            o[i * THREADS] = z;
    } else {
        const float4* __restrict__ src = x + base
            - (m == 1 ? (long long)K_SHIFT * C * VEC_PER_PLANE : 0LL);
        float4 v[VPT];
        #pragma unroll
        for (int i = 0; i < VPT; i++)
            v[i] = src[i * THREADS];
        #pragma unroll
        for (int i = 0; i < VPT; i++)
            o[i * THREADS] = v[i];
    }
}

extern "C" void kernel_launch(void* const* d_in, const int* in_sizes, int n_in,
                              void* d_out, int out_size) {
    const float4* x = (const float4*)d_in[0];
    float4* out = (float4*)d_out;
    tsm_kernel<<<PLANES, THREADS>>>(x, out);
}

// round 3
// speedup vs baseline: 1.0402x; 1.0126x over previous
#include <cuda_runtime.h>

// TSM for fixed shape x=[8,16,96,112,112] fp32, k=4, elements=3.
//   c%3==0: out[t] = (t < 12) ? 0 : x[t]
//   c%3==1: out[t] = (t <  4) ? 0 : x[t-4]
//   c%3==2: out[t] = x[t]
// Plane (b,t,c) = 12544 floats = 3136 float4. One block = HALF a plane:
// 224 threads x 7 float4 = 1568 vecs. 224-thread blocks give 9 blocks/SM
// = 2016 threads (98.4% occupancy) at 32 regs/thread.

static constexpr int B = 8;
static constexpr int T = 16;
static constexpr int C = 96;
static constexpr int HW = 112 * 112;          // 12544
static constexpr int VEC_PER_PLANE = HW / 4;  // 3136
static constexpr int K_SHIFT = 4;
static constexpr int PLANES = B * T * C;      // 12288
static constexpr int THREADS = 224;
static constexpr int VPT = 7;                 // 224*7 = 1568 = plane/2
static constexpr int HALF_VEC = THREADS * VPT;

__global__ __launch_bounds__(THREADS)
void tsm_kernel(const float4* __restrict__ x, float4* __restrict__ out) {
    const int blk   = blockIdx.x;
    const int plane = blk >> 1;
    const int half  = blk & 1;

    const int c = plane % C;
    const int t = (plane / C) % T;
    const int m = c % 3;

    const long long base = (long long)plane * VEC_PER_PLANE
                         + half * HALF_VEC + threadIdx.x;
    float4* __restrict__ o = out + base;

    const bool zero = (m == 0 && t < T - K_SHIFT) || (m == 1 && t < K_SHIFT);

    if (zero) {
        const float4 z = make_float4(0.f, 0.f, 0.f, 0.f);
        #pragma unroll
        for (int i = 0; i < VPT; i++)
            __stcs(&o[i * THREADS], z);
    } else {
        const float4* __restrict__ src = x + base
            - (m == 1 ? (long long)K_SHIFT * C * VEC_PER_PLANE : 0LL);
        float4 v[VPT];
        #pragma unroll
        for (int i = 0; i < VPT; i++)
            v[i] = __ldcs(&src[i * THREADS]);
        #pragma unroll
        for (int i = 0; i < VPT; i++)
            __stcs(&o[i * THREADS], v[i]);
    }
}

extern "C" void kernel_launch(void* const* d_in, const int* in_sizes, int n_in,
                              void* d_out, int out_size) {
    const float4* x = (const float4*)d_in[0];
    float4* out = (float4*)d_out;
    tsm_kernel<<<PLANES * 2, THREADS>>>(x, out);
}